// round 1
// baseline (speedup 1.0000x reference)
#include <cuda_runtime.h>
#include <cuda_bf16.h>

// Problem constants (match reference)
#define IMG_W 640
#define IMG_H 480
#define BATCH 32
__device__ __constant__ float kFU = 320.0f;
__device__ __constant__ float kFV = 320.0f;

static constexpr float H_CU = (IMG_W - 1) / 2.0f;   // 319.5
static constexpr float H_CV = (IMG_H - 1) / 2.0f;   // 239.5
static constexpr float H_BASE = 0.25f;
static constexpr long long NPIX = (long long)BATCH * IMG_H * IMG_W;  // 9,830,400
static constexpr int PLANE = IMG_H * IMG_W;  // 307200

// Scratch accumulator (device global — no allocation allowed)
__device__ double g_sum;

__global__ void pl_zero_kernel() {
    g_sum = 0.0;
}

__global__ void pl_loss_kernel(const float* __restrict__ right,
                               const float* __restrict__ left,
                               const float* __restrict__ depth) {
    const float CUc = H_CU, CVc = H_CV;
    long long idx = (long long)blockIdx.x * blockDim.x + threadIdx.x;

    float contrib = 0.0f;
    if (idx < NPIX) {
        int u = (int)(idx % IMG_W);
        long long t = idx / IMG_W;
        int v = (int)(t % IMG_H);
        int b = (int)(t / IMG_H);
        int pix = v * IMG_W + u;

        float d = depth[(size_t)b * PLANE + pix];

        // Reproject (replicate reference math exactly in fp32)
        float Xcam = ((float)u - CUc) / kFU;
        float Ycam = ((float)v - CVc) / kFV;
        float Z = fmaxf(d, 0.001f);
        float Up = kFU * (d * Xcam + H_BASE) / Z + CUc;
        float Vp = kFV * (d * Ycam) / Z + CVc;

        float un = 2.0f * Up / (float)(IMG_W - 1) - 1.0f;
        float vn = 2.0f * Vp / (float)(IMG_H - 1) - 1.0f;
        if (fabsf(un) > 1.0f) un = 2.0f;
        if (fabsf(vn) > 1.0f) vn = 2.0f;

        // grid_sample bilinear, zeros padding, align_corners=False
        float x = ((un + 1.0f) * (float)IMG_W - 1.0f) * 0.5f;
        float y = ((vn + 1.0f) * (float)IMG_H - 1.0f) * 0.5f;
        float xf = floorf(x), yf = floorf(y);
        float wx1 = x - xf, wy1 = y - yf;
        float wx0 = 1.0f - wx1, wy0 = 1.0f - wy1;
        int x0 = (int)xf, y0 = (int)yf;
        int x1 = x0 + 1, y1 = y0 + 1;

        bool vx0 = (x0 >= 0) && (x0 < IMG_W);
        bool vx1 = (x1 >= 0) && (x1 < IMG_W);
        bool vy0 = (y0 >= 0) && (y0 < IMG_H);
        bool vy1 = (y1 >= 0) && (y1 < IMG_H);

        float w00 = wy0 * wx0, w01 = wy0 * wx1;
        float w10 = wy1 * wx0, w11 = wy1 * wx1;

        int o00 = y0 * IMG_W + x0;
        int o01 = y0 * IMG_W + x1;
        int o10 = y1 * IMG_W + x0;
        int o11 = y1 * IMG_W + x1;

        const float* Lb = left + (size_t)b * 3 * PLANE;
        const float* Rb = right + (size_t)b * 3 * PLANE;

        float diff = 0.0f, sumw = 0.0f, suml = 0.0f;
#pragma unroll
        for (int c = 0; c < 3; c++) {
            const float* ch = Lb + c * PLANE;
            float p00 = (vy0 && vx0) ? __ldg(ch + o00) : 0.0f;
            float p01 = (vy0 && vx1) ? __ldg(ch + o01) : 0.0f;
            float p10 = (vy1 && vx0) ? __ldg(ch + o10) : 0.0f;
            float p11 = (vy1 && vx1) ? __ldg(ch + o11) : 0.0f;
            float wc = p00 * w00 + p01 * w01 + p10 * w10 + p11 * w11;
            sumw += wc;
            float r = __ldg(Rb + c * PLANE + pix);
            diff += fabsf(wc - r);
            suml += __ldg(ch + pix);
        }
        contrib = (sumw > 0.0f && suml > 0.0f) ? diff : 0.0f;
    }

    // Block reduction: warp shuffle then shared, one double atomicAdd per block
    unsigned mask = 0xFFFFFFFFu;
#pragma unroll
    for (int off = 16; off > 0; off >>= 1)
        contrib += __shfl_down_sync(mask, contrib, off);

    __shared__ float s_warp[8];
    int lane = threadIdx.x & 31;
    int wid = threadIdx.x >> 5;
    if (lane == 0) s_warp[wid] = contrib;
    __syncthreads();
    if (wid == 0) {
        float bs = (lane < (blockDim.x >> 5)) ? s_warp[lane] : 0.0f;
#pragma unroll
        for (int off = 4; off > 0; off >>= 1)
            bs += __shfl_down_sync(mask, bs, off);
        if (lane == 0)
            atomicAdd(&g_sum, (double)bs);
    }
}

__global__ void pl_finalize_kernel(float* __restrict__ out) {
    out[0] = (float)(g_sum / (double)NPIX);
}

extern "C" void kernel_launch(void* const* d_in, const int* in_sizes, int n_in,
                              void* d_out, int out_size) {
    const float* rgb_right = (const float*)d_in[0];
    const float* rgb_left = (const float*)d_in[1];
    const float* depth_right = (const float*)d_in[2];
    float* out = (float*)d_out;

    pl_zero_kernel<<<1, 1>>>();
    const int TPB = 256;
    long long nblk = (NPIX + TPB - 1) / TPB;  // 38400
    pl_loss_kernel<<<(unsigned)nblk, TPB>>>(rgb_right, rgb_left, depth_right);
    pl_finalize_kernel<<<1, 1>>>(out);
}

// round 2
// speedup vs baseline: 1.1526x; 1.1526x over previous
#include <cuda_runtime.h>
#include <cuda_bf16.h>

#define IMG_W 640
#define IMG_H 480
#define BATCH 32

static constexpr float H_FU = 320.0f;
static constexpr float H_FV = 320.0f;
static constexpr float H_CU = (IMG_W - 1) / 2.0f;   // 319.5
static constexpr float H_CV = (IMG_H - 1) / 2.0f;   // 239.5
static constexpr float H_BASE = 0.25f;
static constexpr long long NPIX = (long long)BATCH * IMG_H * IMG_W;  // 9,830,400
static constexpr int PLANE = IMG_H * IMG_W;          // 307200
static constexpr int TPB = 256;
static constexpr int QUADS = (int)(NPIX / 4);        // 2,457,600
static constexpr int NBLK = QUADS / TPB;             // 9600

// Per-block partial sums (no allocation allowed -> device global)
__device__ float g_part[NBLK];

__device__ __forceinline__ float pixel_contrib(
    const float* __restrict__ Lb, const float* __restrict__ rightv,
    const float* __restrict__ leftv, int u, int v, float d)
{
    // Reproject (replicate reference fp32 math exactly)
    float Xcam = ((float)u - H_CU) / H_FU;
    float Ycam = ((float)v - H_CV) / H_FV;
    float Z = fmaxf(d, 0.001f);
    float Up = H_FU * (d * Xcam + H_BASE) / Z + H_CU;
    float Vp = H_FV * (d * Ycam) / Z + H_CV;

    float un = 2.0f * Up / (float)(IMG_W - 1) - 1.0f;
    float vn = 2.0f * Vp / (float)(IMG_H - 1) - 1.0f;
    if (fabsf(un) > 1.0f) un = 2.0f;
    if (fabsf(vn) > 1.0f) vn = 2.0f;

    // grid_sample bilinear, zeros padding, align_corners=False
    float x = ((un + 1.0f) * (float)IMG_W - 1.0f) * 0.5f;
    float y = ((vn + 1.0f) * (float)IMG_H - 1.0f) * 0.5f;
    float xf = floorf(x), yf = floorf(y);
    float wx1 = x - xf, wy1 = y - yf;
    float wx0 = 1.0f - wx1, wy0 = 1.0f - wy1;
    int x0 = (int)xf, y0 = (int)yf;
    int x1 = x0 + 1, y1 = y0 + 1;

    bool vx0 = (x0 >= 0) && (x0 < IMG_W);
    bool vx1 = (x1 >= 0) && (x1 < IMG_W);
    bool vy0 = (y0 >= 0) && (y0 < IMG_H);
    bool vy1 = (y1 >= 0) && (y1 < IMG_H);

    float w00 = wy0 * wx0, w01 = wy0 * wx1;
    float w10 = wy1 * wx0, w11 = wy1 * wx1;

    int o00 = y0 * IMG_W + x0;
    int o01 = y0 * IMG_W + x1;
    int o10 = y1 * IMG_W + x0;
    int o11 = y1 * IMG_W + x1;

    float diff = 0.0f, sumw = 0.0f, suml = 0.0f;
#pragma unroll
    for (int c = 0; c < 3; c++) {
        const float* ch = Lb + c * PLANE;
        float p00 = (vy0 && vx0) ? __ldg(ch + o00) : 0.0f;
        float p01 = (vy0 && vx1) ? __ldg(ch + o01) : 0.0f;
        float p10 = (vy1 && vx0) ? __ldg(ch + o10) : 0.0f;
        float p11 = (vy1 && vx1) ? __ldg(ch + o11) : 0.0f;
        float wc = p00 * w00 + p01 * w01 + p10 * w10 + p11 * w11;
        sumw += wc;
        diff += fabsf(wc - rightv[c]);
        suml += leftv[c];
    }
    return (sumw > 0.0f && suml > 0.0f) ? diff : 0.0f;
}

__global__ void __launch_bounds__(TPB)
pl_loss_kernel(const float* __restrict__ right,
               const float* __restrict__ left,
               const float* __restrict__ depth)
{
    int quad = blockIdx.x * TPB + threadIdx.x;    // < QUADS always (exact grid)
    int i0 = quad * 4;                            // first pixel of the 4-group
    int u0 = i0 % IMG_W;                          // multiple of 4
    int t = i0 / IMG_W;
    int v = t % IMG_H;
    int b = t / IMG_H;
    int pix = v * IMG_W + u0;

    const float* Lb = left + (size_t)b * 3 * PLANE;
    const float* Rb = right + (size_t)b * 3 * PLANE;

    // Vector loads: depth, right (3ch), left-at-pix (3ch)
    float4 d4 = *(const float4*)(depth + (size_t)b * PLANE + pix);
    float4 r0 = *(const float4*)(Rb + 0 * PLANE + pix);
    float4 r1 = *(const float4*)(Rb + 1 * PLANE + pix);
    float4 r2 = *(const float4*)(Rb + 2 * PLANE + pix);
    float4 l0 = *(const float4*)(Lb + 0 * PLANE + pix);
    float4 l1 = *(const float4*)(Lb + 1 * PLANE + pix);
    float4 l2 = *(const float4*)(Lb + 2 * PLANE + pix);

    float darr[4] = {d4.x, d4.y, d4.z, d4.w};
    float rarr[4][3] = {{r0.x, r1.x, r2.x}, {r0.y, r1.y, r2.y},
                        {r0.z, r1.z, r2.z}, {r0.w, r1.w, r2.w}};
    float larr[4][3] = {{l0.x, l1.x, l2.x}, {l0.y, l1.y, l2.y},
                        {l0.z, l1.z, l2.z}, {l0.w, l1.w, l2.w}};

    float acc = 0.0f;
#pragma unroll
    for (int j = 0; j < 4; j++)
        acc += pixel_contrib(Lb, rarr[j], larr[j], u0 + j, v, darr[j]);

    // Block reduction -> one partial per block
    unsigned mask = 0xFFFFFFFFu;
#pragma unroll
    for (int off = 16; off > 0; off >>= 1)
        acc += __shfl_down_sync(mask, acc, off);

    __shared__ float s_warp[TPB / 32];
    int lane = threadIdx.x & 31;
    int wid = threadIdx.x >> 5;
    if (lane == 0) s_warp[wid] = acc;
    __syncthreads();
    if (wid == 0) {
        float bs = (lane < (TPB / 32)) ? s_warp[lane] : 0.0f;
#pragma unroll
        for (int off = 4; off > 0; off >>= 1)
            bs += __shfl_down_sync(mask, bs, off);
        if (lane == 0)
            g_part[blockIdx.x] = bs;
    }
}

__global__ void __launch_bounds__(1024)
pl_finalize_kernel(float* __restrict__ out)
{
    // Deterministic tree-sum of NBLK partials
    double acc = 0.0;
    for (int i = threadIdx.x; i < NBLK; i += 1024)
        acc += (double)g_part[i];

    unsigned mask = 0xFFFFFFFFu;
#pragma unroll
    for (int off = 16; off > 0; off >>= 1)
        acc += __shfl_down_sync(mask, acc, off);

    __shared__ double s_warp[32];
    int lane = threadIdx.x & 31;
    int wid = threadIdx.x >> 5;
    if (lane == 0) s_warp[wid] = acc;
    __syncthreads();
    if (wid == 0) {
        double bs = (lane < 32) ? s_warp[lane] : 0.0;
#pragma unroll
        for (int off = 16; off > 0; off >>= 1)
            bs += __shfl_down_sync(mask, bs, off);
        if (lane == 0)
            out[0] = (float)(bs / (double)NPIX);
    }
}

extern "C" void kernel_launch(void* const* d_in, const int* in_sizes, int n_in,
                              void* d_out, int out_size) {
    const float* rgb_right = (const float*)d_in[0];
    const float* rgb_left = (const float*)d_in[1];
    const float* depth_right = (const float*)d_in[2];
    float* out = (float*)d_out;

    pl_loss_kernel<<<NBLK, TPB>>>(rgb_right, rgb_left, depth_right);
    pl_finalize_kernel<<<1, 1024>>>(out);
}